// round 2
// baseline (speedup 1.0000x reference)
#include <cuda_runtime.h>
#include <cuda_bf16.h>
#include <math.h>

// Problem dims (fixed per reference)
#define T_DIM 256
#define B_DIM 256
#define V_DIM 512
#define H_DIM 1024
#define M_ALL (T_DIM * B_DIM)          // 65536
#define BH    (B_DIM * H_DIM)          // 262144
#define TBV   (T_DIM * B_DIM * V_DIM)  // 33554432

// Scratch (allocation-free rule): 3 x 256 MB
__device__ float g_xh [(size_t)M_ALL * H_DIM];          // xh   [T*B][H]
__device__ float g_xhT[(size_t)T_DIM * H_DIM * B_DIM];  // xh^T [T][H][B]
__device__ float g_hsT[(size_t)T_DIM * H_DIM * B_DIM];  // hs^T [T][H][B]

// ---------------------------------------------------------------------------
// packed f32x2 helpers (Blackwell-only FFMA2 path; 2x fp32 FMA throughput)
// ---------------------------------------------------------------------------
__device__ __forceinline__ unsigned long long dup2(float v) {
    unsigned long long r;
    asm("mov.b64 %0,{%1,%1};" : "=l"(r) : "f"(v));
    return r;
}
__device__ __forceinline__ void fma2(unsigned long long& d,
                                     unsigned long long a,
                                     unsigned long long b) {
    asm("fma.rn.f32x2 %0,%1,%2,%0;" : "+l"(d) : "l"(a), "l"(b));
}
__device__ __forceinline__ float2 unpk(unsigned long long v) {
    float2 f;
    asm("mov.b64 {%0,%1},%2;" : "=f"(f.x), "=f"(f.y) : "l"(v));
    return f;
}

// ---------------------------------------------------------------------------
// Classic fp32 SGEMM: C[M,N] = A[M,K] @ B[K,N] + bias[N]   (A row-major)
// BM=128, BN=128, BK=8, 256 threads, 8x8 per thread.
// ---------------------------------------------------------------------------
__global__ void __launch_bounds__(256)
sgemm_bias_kernel(const float* __restrict__ A, const float* __restrict__ B,
                  const float* __restrict__ bias, float* __restrict__ C,
                  int M, int N, int K)
{
    constexpr int BM = 128, BN = 128, BK = 8, TM = 8, TN = 8;
    __shared__ float As[BK][BM];
    __shared__ float Bs[BK][BN];

    const int tid = threadIdx.x;
    const int bm = blockIdx.y * BM;
    const int bn = blockIdx.x * BN;

    const int tx = tid % (BN / TN);
    const int ty = tid / (BN / TN);
    const int row0 = ty * TM;
    const int col0 = tx * TN;

    const int aRow  = tid / (BK / 4);
    const int aCol4 = (tid % (BK / 4)) * 4;
    const int bRow  = tid / (BN / 4);
    const int bCol4 = (tid % (BN / 4)) * 4;

    const float* Aptr = A + (size_t)bm * K;
    const float* Bptr = B + bn;

    float acc[TM][TN];
#pragma unroll
    for (int i = 0; i < TM; i++)
#pragma unroll
        for (int j = 0; j < TN; j++) acc[i][j] = 0.0f;

    for (int k0 = 0; k0 < K; k0 += BK) {
        float4 a4 = *(const float4*)(Aptr + (size_t)aRow * K + k0 + aCol4);
        As[aCol4 + 0][aRow] = a4.x;
        As[aCol4 + 1][aRow] = a4.y;
        As[aCol4 + 2][aRow] = a4.z;
        As[aCol4 + 3][aRow] = a4.w;
        *(float4*)&Bs[bRow][bCol4] =
            *(const float4*)(Bptr + (size_t)(k0 + bRow) * N + bCol4);
        __syncthreads();

#pragma unroll
        for (int k = 0; k < BK; k++) {
            float ra[TM], rb[TN];
#pragma unroll
            for (int i = 0; i < TM; i++) ra[i] = As[k][row0 + i];
#pragma unroll
            for (int j = 0; j < TN; j++) rb[j] = Bs[k][col0 + j];
#pragma unroll
            for (int i = 0; i < TM; i++)
#pragma unroll
                for (int j = 0; j < TN; j++)
                    acc[i][j] = fmaf(ra[i], rb[j], acc[i][j]);
        }
        __syncthreads();
    }

#pragma unroll
    for (int i = 0; i < TM; i++) {
        const size_t gr = (size_t)(bm + row0 + i);
#pragma unroll
        for (int j = 0; j < TN; j += 4) {
            const int gc = bn + col0 + j;
            float4 bv = *(const float4*)(bias + gc);
            float4 v;
            v.x = acc[i][j + 0] + bv.x;
            v.y = acc[i][j + 1] + bv.y;
            v.z = acc[i][j + 2] + bv.z;
            v.w = acc[i][j + 3] + bv.w;
            *(float4*)(C + gr * N + gc) = v;
        }
    }
}

// ---------------------------------------------------------------------------
// SGEMM variant with A transposed (k-major): C[M,N] = A_T^T @ B + bias
// A_T: [K][M]. Slices via blockIdx.z: A_T += z*K*M, C += z*M*N.
// Used for GEMM3 consuming hs^T directly.
// ---------------------------------------------------------------------------
__global__ void __launch_bounds__(256)
sgemm_AT_bias_kernel(const float* __restrict__ AT, const float* __restrict__ B,
                     const float* __restrict__ bias, float* __restrict__ C,
                     int M, int N, int K)
{
    constexpr int BM = 128, BN = 128, BK = 8, TM = 8, TN = 8;
    __shared__ float As[BK][BM];
    __shared__ float Bs[BK][BN];

    const int tid = threadIdx.x;
    const int bm = blockIdx.y * BM;
    const int bn = blockIdx.x * BN;

    AT += (size_t)blockIdx.z * K * M;
    C  += (size_t)blockIdx.z * M * N;

    const int tx = tid % (BN / TN);
    const int ty = tid / (BN / TN);
    const int row0 = ty * TM;
    const int col0 = tx * TN;

    // A tile: As[k][m] loaded directly (already k-major): 8 rows x 128 cols
    const int aRow  = tid / 32;        // 0..7  (k)
    const int aCol4 = (tid % 32) * 4;  // 0..124 (m)
    const int bRow  = tid / (BN / 4);
    const int bCol4 = (tid % (BN / 4)) * 4;

    float acc[TM][TN];
#pragma unroll
    for (int i = 0; i < TM; i++)
#pragma unroll
        for (int j = 0; j < TN; j++) acc[i][j] = 0.0f;

    for (int k0 = 0; k0 < K; k0 += BK) {
        *(float4*)&As[aRow][aCol4] =
            *(const float4*)(AT + (size_t)(k0 + aRow) * M + bm + aCol4);
        *(float4*)&Bs[bRow][bCol4] =
            *(const float4*)(B + (size_t)(k0 + bRow) * N + bn + bCol4);
        __syncthreads();

#pragma unroll
        for (int k = 0; k < BK; k++) {
            float ra[TM], rb[TN];
#pragma unroll
            for (int i = 0; i < TM; i++) ra[i] = As[k][row0 + i];
#pragma unroll
            for (int j = 0; j < TN; j++) rb[j] = Bs[k][col0 + j];
#pragma unroll
            for (int i = 0; i < TM; i++)
#pragma unroll
                for (int j = 0; j < TN; j++)
                    acc[i][j] = fmaf(ra[i], rb[j], acc[i][j]);
        }
        __syncthreads();
    }

#pragma unroll
    for (int i = 0; i < TM; i++) {
        const size_t gr = (size_t)(bm + row0 + i);
#pragma unroll
        for (int j = 0; j < TN; j += 4) {
            const int gc = bn + col0 + j;
            float4 bv = *(const float4*)(bias + gc);
            float4 v;
            v.x = acc[i][j + 0] + bv.x;
            v.y = acc[i][j + 1] + bv.y;
            v.z = acc[i][j + 2] + bv.z;
            v.w = acc[i][j + 3] + bv.w;
            *(float4*)(C + gr * N + gc) = v;
        }
    }
}

// ---------------------------------------------------------------------------
// Recurrence step, transposed layout:
//   oT[n][b] = tanh(xT[n][b] + sum_k W[k][n] * hT[k][b])
// hT/xT/oT: [1024][256].  W: [1024][1024] (row = k, col = n).
// Tile: 32 n x 64 b, BK=32. 128 threads. grid = (32 n-tiles, 4 b-tiles) = 128.
// Each thread: 1 n column x 16 b as 8 packed f32x2 accumulators.
// ---------------------------------------------------------------------------
__global__ void __launch_bounds__(128)
rnn_step_T_kernel(const float* __restrict__ hT,
                  const float* __restrict__ W,
                  const float* __restrict__ xT,
                  float* __restrict__ oT)
{
    constexpr int BN = 32, BB = 64, BK = 32;
    constexpr int NCHUNK = H_DIM / BK;  // 32

    __shared__ __align__(16) float Hs[2][BK][BB];  // 8 KB x2
    __shared__ __align__(16) float Ws[2][BK][BN];  // 4 KB x2

    const int tid = threadIdx.x;
    const int n0 = blockIdx.x * BN;
    const int b0 = blockIdx.y * BB;

    const int nloc = tid >> 2;         // 0..31
    const int bsub = (tid & 3) * 16;   // 0,16,32,48

    // gmem staging indices
    // H chunk: 32x64 floats = 512 float4, 4 per thread
    // W chunk: 32x32 floats = 256 float4, 2 per thread
    float4 hreg[4], wreg[2];

    auto ldg_chunk = [&](int kc) {
#pragma unroll
        for (int i = 0; i < 4; i++) {
            int idx = tid + 128 * i;            // 0..511
            int row = idx >> 4;                 // 0..31
            int col = (idx & 15) << 2;          // 0..60
            hreg[i] = *(const float4*)(hT + (size_t)(kc * BK + row) * B_DIM + b0 + col);
        }
#pragma unroll
        for (int i = 0; i < 2; i++) {
            int idx = tid + 128 * i;            // 0..255
            int row = idx >> 3;                 // 0..31
            int col = (idx & 7) << 2;           // 0..28
            wreg[i] = *(const float4*)(W + (size_t)(kc * BK + row) * H_DIM + n0 + col);
        }
    };
    auto sts_chunk = [&](int buf) {
#pragma unroll
        for (int i = 0; i < 4; i++) {
            int idx = tid + 128 * i;
            int row = idx >> 4;
            int col = (idx & 15) << 2;
            *(float4*)&Hs[buf][row][col] = hreg[i];
        }
#pragma unroll
        for (int i = 0; i < 2; i++) {
            int idx = tid + 128 * i;
            int row = idx >> 3;
            int col = (idx & 7) << 2;
            *(float4*)&Ws[buf][row][col] = wreg[i];
        }
    };

    unsigned long long acc[8];
#pragma unroll
    for (int j = 0; j < 8; j++) acc[j] = 0ull;  // {0.f,0.f}

    ldg_chunk(0);
    sts_chunk(0);
    __syncthreads();

    for (int kc = 0; kc < NCHUNK; kc++) {
        const int buf = kc & 1;
        if (kc + 1 < NCHUNK) ldg_chunk(kc + 1);  // issue early, hidden by compute

#pragma unroll 4
        for (int k = 0; k < BK; k++) {
            const unsigned long long w2 = dup2(Ws[buf][k][nloc]);
            const ulonglong2* hp =
                reinterpret_cast<const ulonglong2*>(&Hs[buf][k][bsub]);
            ulonglong2 p0 = hp[0];
            ulonglong2 p1 = hp[1];
            ulonglong2 p2 = hp[2];
            ulonglong2 p3 = hp[3];
            fma2(acc[0], p0.x, w2);
            fma2(acc[1], p0.y, w2);
            fma2(acc[2], p1.x, w2);
            fma2(acc[3], p1.y, w2);
            fma2(acc[4], p2.x, w2);
            fma2(acc[5], p2.y, w2);
            fma2(acc[6], p3.x, w2);
            fma2(acc[7], p3.y, w2);
        }

        if (kc + 1 < NCHUNK) sts_chunk(1 - buf);
        __syncthreads();
    }

    // Epilogue: += xh, tanh, store (coalesced along b)
    const int n = n0 + nloc;
    const float* xrow = xT + (size_t)n * B_DIM + b0 + bsub;
    float*       orow = oT + (size_t)n * B_DIM + b0 + bsub;
#pragma unroll
    for (int jj = 0; jj < 4; jj++) {
        float4 x4 = ((const float4*)xrow)[jj];
        float2 a0 = unpk(acc[2 * jj]);
        float2 a1 = unpk(acc[2 * jj + 1]);
        float4 o;
        o.x = tanhf(a0.x + x4.x);
        o.y = tanhf(a0.y + x4.y);
        o.z = tanhf(a1.x + x4.z);
        o.w = tanhf(a1.y + x4.w);
        ((float4*)orow)[jj] = o;
    }
}

// ---------------------------------------------------------------------------
// Tiled transpose: out[c][r] = in[r][c] per slice (blockIdx.z).
// in: [rows][cols]. block 32x8, 32x32 tiles.
// ---------------------------------------------------------------------------
__global__ void __launch_bounds__(256)
transpose_slice_kernel(const float* __restrict__ in, float* __restrict__ out,
                       int rows, int cols)
{
    __shared__ float tile[32][33];
    const size_t base = (size_t)blockIdx.z * rows * cols;
    const int c0 = blockIdx.x * 32;
    const int r0 = blockIdx.y * 32;
    const int tx = threadIdx.x;
    const int ty = threadIdx.y;

#pragma unroll
    for (int i = 0; i < 32; i += 8)
        tile[ty + i][tx] = in[base + (size_t)(r0 + ty + i) * cols + c0 + tx];
    __syncthreads();
#pragma unroll
    for (int i = 0; i < 32; i += 8)
        out[base + (size_t)(c0 + ty + i) * rows + r0 + tx] = tile[tx][ty + i];
}

// h_0 = tanh(xh_0)  (elementwise on transposed slice)
__global__ void __launch_bounds__(256)
tanh_kernel(const float* __restrict__ x, float* __restrict__ y)
{
    const size_t i = ((size_t)blockIdx.x * blockDim.x + threadIdx.x) * 4;
    float4 v = *(const float4*)(x + i);
    v.x = tanhf(v.x);
    v.y = tanhf(v.y);
    v.z = tanhf(v.z);
    v.w = tanhf(v.w);
    *(float4*)(y + i) = v;
}

// ---------------------------------------------------------------------------
extern "C" void kernel_launch(void* const* d_in, const int* in_sizes, int n_in,
                              void* d_out, int out_size)
{
    const float* inputs  = (const float*)d_in[0]; // [T,B,V]
    const float* W_xh    = (const float*)d_in[1]; // [V,H]
    const float* W_hh    = (const float*)d_in[2]; // [H,H]
    const float* b_h     = (const float*)d_in[3]; // [H]
    const float* W_dense = (const float*)d_in[4]; // [H,V]
    const float* b_dense = (const float*)d_in[5]; // [V]
    float* out = (float*)d_out;

    float *xh = nullptr, *xhT = nullptr, *hsT = nullptr;
    cudaGetSymbolAddress((void**)&xh,  g_xh);
    cudaGetSymbolAddress((void**)&xhT, g_xhT);
    cudaGetSymbolAddress((void**)&hsT, g_hsT);

    // 1) xh = inputs @ W_xh + b_h : [65536,512] x [512,1024]
    {
        dim3 grid(H_DIM / 128, M_ALL / 128);
        sgemm_bias_kernel<<<grid, 256>>>(inputs, W_xh, b_h, xh,
                                         M_ALL, H_DIM, V_DIM);
    }

    // 2) transpose each timestep: xh[t][B][H] -> xhT[t][H][B]
    {
        dim3 grid(H_DIM / 32, B_DIM / 32, T_DIM);
        dim3 block(32, 8);
        transpose_slice_kernel<<<grid, block>>>(xh, xhT, B_DIM, H_DIM);
    }

    // 3) recurrence in transposed space
    {
        tanh_kernel<<<BH / (256 * 4), 256>>>(xhT, hsT);  // h_0
        dim3 grid(H_DIM / 32, B_DIM / 64);               // (32, 4) = 128 blocks
        for (int t = 1; t < T_DIM; t++) {
            rnn_step_T_kernel<<<grid, 128>>>(hsT + (size_t)(t - 1) * BH, W_hh,
                                             xhT + (size_t)t * BH,
                                             hsT + (size_t)t * BH);
        }
    }

    // 4) outputs = hs @ W_dense + b_dense, consuming hs^T per timestep
    {
        dim3 grid(V_DIM / 128, B_DIM / 128, T_DIM);  // (4, 2, 256)
        sgemm_AT_bias_kernel<<<grid, 256>>>(hsT, W_dense, b_dense, out,
                                            B_DIM, V_DIM, H_DIM);
    }

    // 5) final state: hsT[T-1] [H][B] -> out+TBV [B][H]
    if (out_size >= TBV + BH) {
        dim3 grid(B_DIM / 32, H_DIM / 32, 1);
        dim3 block(32, 8);
        transpose_slice_kernel<<<grid, block>>>(hsT + (size_t)(T_DIM - 1) * BH,
                                                out + TBV, H_DIM, B_DIM);
    }
}

// round 3
// speedup vs baseline: 2.4878x; 2.4878x over previous
#include <cuda_runtime.h>
#include <cuda_bf16.h>
#include <math.h>

// Problem dims (fixed per reference)
#define T_DIM 256
#define B_DIM 256
#define V_DIM 512
#define H_DIM 1024
#define M_ALL (T_DIM * B_DIM)          // 65536
#define BH    (B_DIM * H_DIM)          // 262144
#define TBV   (T_DIM * B_DIM * V_DIM)  // 33554432

// Scratch (allocation-free rule)
__device__ float g_xh[(size_t)M_ALL * H_DIM];   // xh [T*B][H]  256 MB
__device__ float g_hs[(size_t)M_ALL * H_DIM];   // hs [T*B][H]  256 MB
__device__ float g_part[4 * BH];                // split-K partials, 4 MB
__device__ unsigned g_cnt[32];                  // per-tile arrival counters (zero-init)

// ---------------------------------------------------------------------------
// packed f32x2 helpers (Blackwell FFMA2: 2x fp32 FMA throughput)
// ---------------------------------------------------------------------------
__device__ __forceinline__ unsigned long long dup2(float v) {
    unsigned long long r;
    asm("mov.b64 %0,{%1,%1};" : "=l"(r) : "f"(v));
    return r;
}
__device__ __forceinline__ void fma2(unsigned long long& d,
                                     unsigned long long a,
                                     unsigned long long b) {
    asm("fma.rn.f32x2 %0,%1,%2,%0;" : "+l"(d) : "l"(a), "l"(b));
}
__device__ __forceinline__ float2 unpk(unsigned long long v) {
    float2 f;
    asm("mov.b64 {%0,%1},%2;" : "=f"(f.x), "=f"(f.y) : "l"(v));
    return f;
}

// ---------------------------------------------------------------------------
// fp32 SGEMM with f32x2 inner loop: C[M,N] = A[M,K] @ B[K,N] + bias[N]
// BM=128, BN=128, BK=8, 256 threads, 8x8 per thread (n packed in pairs).
// ---------------------------------------------------------------------------
__global__ void __launch_bounds__(256)
sgemm_bias_kernel(const float* __restrict__ A, const float* __restrict__ B,
                  const float* __restrict__ bias, float* __restrict__ C,
                  int M, int N, int K)
{
    constexpr int BM = 128, BN = 128, BK = 8, TM = 8, TN = 8;
    __shared__ __align__(16) float As[BK][BM];
    __shared__ __align__(16) float Bs[BK][BN];

    const int tid = threadIdx.x;
    const int bm = blockIdx.y * BM;
    const int bn = blockIdx.x * BN;

    const int tx = tid % (BN / TN);   // 0..15
    const int ty = tid / (BN / TN);   // 0..15
    const int row0 = ty * TM;
    const int col0 = tx * TN;         // 8-aligned -> 32B-aligned in smem

    const int aRow  = tid / (BK / 4);
    const int aCol4 = (tid % (BK / 4)) * 4;
    const int bRow  = tid / (BN / 4);
    const int bCol4 = (tid % (BN / 4)) * 4;

    const float* Aptr = A + (size_t)bm * K;
    const float* Bptr = B + bn;

    unsigned long long acc[TM][TN / 2];
#pragma unroll
    for (int i = 0; i < TM; i++)
#pragma unroll
        for (int j = 0; j < TN / 2; j++) acc[i][j] = 0ull;

    for (int k0 = 0; k0 < K; k0 += BK) {
        float4 a4 = *(const float4*)(Aptr + (size_t)aRow * K + k0 + aCol4);
        As[aCol4 + 0][aRow] = a4.x;
        As[aCol4 + 1][aRow] = a4.y;
        As[aCol4 + 2][aRow] = a4.z;
        As[aCol4 + 3][aRow] = a4.w;
        *(float4*)&Bs[bRow][bCol4] =
            *(const float4*)(Bptr + (size_t)(k0 + bRow) * N + bCol4);
        __syncthreads();

#pragma unroll
        for (int k = 0; k < BK; k++) {
            unsigned long long ra[TM];
#pragma unroll
            for (int i = 0; i < TM; i++) ra[i] = dup2(As[k][row0 + i]);
            const ulonglong2* bp = (const ulonglong2*)&Bs[k][col0];
            ulonglong2 rb0 = bp[0];
            ulonglong2 rb1 = bp[1];
#pragma unroll
            for (int i = 0; i < TM; i++) {
                fma2(acc[i][0], ra[i], rb0.x);
                fma2(acc[i][1], ra[i], rb0.y);
                fma2(acc[i][2], ra[i], rb1.x);
                fma2(acc[i][3], ra[i], rb1.y);
            }
        }
        __syncthreads();
    }

    // Epilogue: unpack, add bias, store
    float4 bv0 = *(const float4*)(bias + bn + col0);
    float4 bv1 = *(const float4*)(bias + bn + col0 + 4);
#pragma unroll
    for (int i = 0; i < TM; i++) {
        const size_t gr = (size_t)(bm + row0 + i);
        float2 a0 = unpk(acc[i][0]);
        float2 a1 = unpk(acc[i][1]);
        float2 a2 = unpk(acc[i][2]);
        float2 a3 = unpk(acc[i][3]);
        float4 v0 = make_float4(a0.x + bv0.x, a0.y + bv0.y,
                                a1.x + bv0.z, a1.y + bv0.w);
        float4 v1 = make_float4(a2.x + bv1.x, a2.y + bv1.y,
                                a3.x + bv1.z, a3.y + bv1.w);
        *(float4*)(C + gr * N + bn + col0)     = v0;
        *(float4*)(C + gr * N + bn + col0 + 4) = v1;
    }
}

// ---------------------------------------------------------------------------
// Recurrence step, split-K with fused reduction:
//   h_out[b][n] = tanh(xh_t[b][n] + sum_k h_prev[b][k] * W[k][n])
// Grid: (8 n-tiles of 128, 4 b-tiles of 64, 4 k-splits of 256) = 128 blocks.
// Block: 256 threads, thread tile 4b x 8n (16 f32x2 accumulators).
// Last-arriving block of each (n,b) tile reduces the 4 partials + tanh.
// ---------------------------------------------------------------------------
__global__ void __launch_bounds__(256)
rnn_step_kernel(const float* __restrict__ h_prev,  // [256][1024]
                const float* __restrict__ W,       // [1024][1024]
                const float* __restrict__ xh_t,    // [256][1024]
                float* __restrict__ h_out)         // [256][1024]
{
    constexpr int BB = 64, BN = 128, BK = 16;
    constexpr int NCHUNK = 256 / BK;  // 16 chunks over this block's k-range

    __shared__ __align__(16) float Hs[2][BB][BK + 1];  // 64 x 17
    __shared__ __align__(16) float Ws[2][BK][BN];
    __shared__ unsigned s_old;

    const int tid = threadIdx.x;
    const int n0 = blockIdx.x * BN;
    const int b0 = blockIdx.y * BB;
    const int k0 = blockIdx.z * 256;
    const int tileid = blockIdx.y * 8 + blockIdx.x;

    // warp layout: lane -> (bgl 0..7, ngl 0..3); warp -> (bgw 0..1, ngw 0..3)
    const int lane = tid & 31;
    const int w    = tid >> 5;
    const int bg = (w & 1) * 8 + (lane >> 2);   // 0..15
    const int ng = (w >> 1) * 4 + (lane & 3);   // 0..15
    const int bb4 = bg * 4;                     // local b base (4 rows)
    const int nn8 = ng * 8;                     // local n base (8 cols)

    // staging indices
    const int hb  = tid >> 2;          // 0..63
    const int hk4 = (tid & 3) * 4;     // 0,4,8,12
    float4 hreg, wreg0, wreg1;

    float* part = g_part + (size_t)blockIdx.z * BH;

    auto ldg_chunk = [&](int c) {
        const int kc = k0 + c * BK;
        hreg  = *(const float4*)(h_prev + (size_t)(b0 + hb) * H_DIM + kc + hk4);
        int i0 = tid, i1 = tid + 256;
        wreg0 = *(const float4*)(W + (size_t)(kc + (i0 >> 5)) * H_DIM + n0 + (i0 & 31) * 4);
        wreg1 = *(const float4*)(W + (size_t)(kc + (i1 >> 5)) * H_DIM + n0 + (i1 & 31) * 4);
    };
    auto sts_chunk = [&](int buf) {
        Hs[buf][hb][hk4 + 0] = hreg.x;
        Hs[buf][hb][hk4 + 1] = hreg.y;
        Hs[buf][hb][hk4 + 2] = hreg.z;
        Hs[buf][hb][hk4 + 3] = hreg.w;
        int i0 = tid, i1 = tid + 256;
        *(float4*)&Ws[buf][i0 >> 5][(i0 & 31) * 4] = wreg0;
        *(float4*)&Ws[buf][i1 >> 5][(i1 & 31) * 4] = wreg1;
    };

    unsigned long long acc[4][4];
#pragma unroll
    for (int i = 0; i < 4; i++)
#pragma unroll
        for (int j = 0; j < 4; j++) acc[i][j] = 0ull;

    ldg_chunk(0);
    sts_chunk(0);
    __syncthreads();

    for (int c = 0; c < NCHUNK; c++) {
        const int buf = c & 1;
        if (c + 1 < NCHUNK) ldg_chunk(c + 1);

#pragma unroll
        for (int kk = 0; kk < BK; kk++) {
            unsigned long long d0 = dup2(Hs[buf][bb4 + 0][kk]);
            unsigned long long d1 = dup2(Hs[buf][bb4 + 1][kk]);
            unsigned long long d2 = dup2(Hs[buf][bb4 + 2][kk]);
            unsigned long long d3 = dup2(Hs[buf][bb4 + 3][kk]);
            const ulonglong2* wp = (const ulonglong2*)&Ws[buf][kk][nn8];
            ulonglong2 wa = wp[0];
            ulonglong2 wb = wp[1];
            fma2(acc[0][0], d0, wa.x); fma2(acc[0][1], d0, wa.y);
            fma2(acc[0][2], d0, wb.x); fma2(acc[0][3], d0, wb.y);
            fma2(acc[1][0], d1, wa.x); fma2(acc[1][1], d1, wa.y);
            fma2(acc[1][2], d1, wb.x); fma2(acc[1][3], d1, wb.y);
            fma2(acc[2][0], d2, wa.x); fma2(acc[2][1], d2, wa.y);
            fma2(acc[2][2], d2, wb.x); fma2(acc[2][3], d2, wb.y);
            fma2(acc[3][0], d3, wa.x); fma2(acc[3][1], d3, wa.y);
            fma2(acc[3][2], d3, wb.x); fma2(acc[3][3], d3, wb.y);
        }

        if (c + 1 < NCHUNK) sts_chunk(1 - buf);
        __syncthreads();
    }

    // Write partial tile (fp32, n-contiguous pairs are already packed)
#pragma unroll
    for (int i = 0; i < 4; i++) {
        float* dst = part + (size_t)(b0 + bb4 + i) * H_DIM + n0 + nn8;
        ((ulonglong2*)dst)[0] = make_ulonglong2(acc[i][0], acc[i][1]);
        ((ulonglong2*)dst)[1] = make_ulonglong2(acc[i][2], acc[i][3]);
    }

    __threadfence();
    if (tid == 0) s_old = atomicAdd(&g_cnt[tileid], 1u);
    __syncthreads();

    if (s_old == 3u) {
        // Last arriver: reduce 4 partials + xh, tanh, store h_out
        __threadfence();  // acquire partials written by other blocks
        const float* p0 = g_part;
        const float* p1 = g_part + BH;
        const float* p2 = g_part + 2 * BH;
        const float* p3 = g_part + 3 * BH;
#pragma unroll
        for (int jj = 0; jj < 8; jj++) {
            int f4 = tid + 256 * jj;           // 0..2047 float4s of the tile
            int bb = f4 >> 5;                  // 0..63
            int nn = (f4 & 31) << 2;           // 0..124
            size_t off = (size_t)(b0 + bb) * H_DIM + n0 + nn;
            float4 a = ((const float4*)(p0 + off))[0];
            float4 b = ((const float4*)(p1 + off))[0];
            float4 c = ((const float4*)(p2 + off))[0];
            float4 d = ((const float4*)(p3 + off))[0];
            float4 x = ((const float4*)(xh_t + off))[0];
            float4 o;
            o.x = tanhf(a.x + b.x + c.x + d.x + x.x);
            o.y = tanhf(a.y + b.y + c.y + d.y + x.y);
            o.z = tanhf(a.z + b.z + c.z + d.z + x.z);
            o.w = tanhf(a.w + b.w + c.w + d.w + x.w);
            ((float4*)(h_out + off))[0] = o;
        }
        if (tid == 0) g_cnt[tileid] = 0u;  // reset for next step / next replay
    }
}

// h_0 = tanh(xh_0)
__global__ void __launch_bounds__(256)
tanh_kernel(const float* __restrict__ x, float* __restrict__ y)
{
    const size_t i = ((size_t)blockIdx.x * blockDim.x + threadIdx.x) * 4;
    float4 v = *(const float4*)(x + i);
    v.x = tanhf(v.x);
    v.y = tanhf(v.y);
    v.z = tanhf(v.z);
    v.w = tanhf(v.w);
    *(float4*)(y + i) = v;
}

__global__ void __launch_bounds__(256)
copy_kernel(const float* __restrict__ src, float* __restrict__ dst)
{
    const size_t i = ((size_t)blockIdx.x * blockDim.x + threadIdx.x) * 4;
    *(float4*)(dst + i) = *(const float4*)(src + i);
}

// ---------------------------------------------------------------------------
extern "C" void kernel_launch(void* const* d_in, const int* in_sizes, int n_in,
                              void* d_out, int out_size)
{
    const float* inputs  = (const float*)d_in[0]; // [T,B,V]
    const float* W_xh    = (const float*)d_in[1]; // [V,H]
    const float* W_hh    = (const float*)d_in[2]; // [H,H]
    const float* b_h     = (const float*)d_in[3]; // [H]
    const float* W_dense = (const float*)d_in[4]; // [H,V]
    const float* b_dense = (const float*)d_in[5]; // [V]
    float* out = (float*)d_out;

    float *xh = nullptr, *hs = nullptr;
    cudaGetSymbolAddress((void**)&xh, g_xh);
    cudaGetSymbolAddress((void**)&hs, g_hs);

    // 1) xh = inputs @ W_xh + b_h : [65536,512] x [512,1024]
    {
        dim3 grid(H_DIM / 128, M_ALL / 128);
        sgemm_bias_kernel<<<grid, 256>>>(inputs, W_xh, b_h, xh,
                                         M_ALL, H_DIM, V_DIM);
    }

    // 2) recurrence (natural [b][h] layout, split-K step kernel)
    {
        tanh_kernel<<<BH / (256 * 4), 256>>>(xh, hs);  // h_0
        dim3 grid(H_DIM / 128, B_DIM / 64, 4);          // 8 x 4 x 4 = 128 blocks
        for (int t = 1; t < T_DIM; t++) {
            rnn_step_kernel<<<grid, 256>>>(hs + (size_t)(t - 1) * BH, W_hh,
                                           xh + (size_t)t * BH,
                                           hs + (size_t)t * BH);
        }
    }

    // 3) outputs = hs @ W_dense + b_dense : [65536,1024] x [1024,512]
    {
        dim3 grid(V_DIM / 128, M_ALL / 128);
        sgemm_bias_kernel<<<grid, 256>>>(hs, W_dense, b_dense, out,
                                         M_ALL, V_DIM, H_DIM);
    }

    // 4) state = h_{T-1}
    if (out_size >= TBV + BH) {
        copy_kernel<<<BH / (256 * 4), 256>>>(hs + (size_t)(T_DIM - 1) * BH,
                                             out + TBV);
    }
}

// round 4
// speedup vs baseline: 2.6792x; 1.0770x over previous
#include <cuda_runtime.h>
#include <cuda_bf16.h>
#include <math.h>

// Problem dims (fixed per reference)
#define T_DIM 256
#define B_DIM 256
#define V_DIM 512
#define H_DIM 1024
#define M_ALL (T_DIM * B_DIM)          // 65536
#define BH    (B_DIM * H_DIM)          // 262144
#define TBV   (T_DIM * B_DIM * V_DIM)  // 33554432

#define KSPLIT 8
#define NBLK   128                      // 8 n-tiles x 2 b-tiles x 8 k-splits

// Scratch (allocation-free rule)
__device__ float g_xh[(size_t)M_ALL * H_DIM];     // 256 MB
__device__ float g_hs[(size_t)M_ALL * H_DIM];     // 256 MB
__device__ float g_part[(size_t)KSPLIT * BH];     // 8 MB split-K partials
__device__ unsigned g_bar;                        // global barrier counter

// ---------------------------------------------------------------------------
// packed f32x2 helpers (Blackwell FFMA2: 2x fp32 FMA throughput)
// ---------------------------------------------------------------------------
__device__ __forceinline__ unsigned long long dup2(float v) {
    unsigned long long r;
    asm("mov.b64 %0,{%1,%1};" : "=l"(r) : "f"(v));
    return r;
}
__device__ __forceinline__ void fma2(unsigned long long& d,
                                     unsigned long long a,
                                     unsigned long long b) {
    asm("fma.rn.f32x2 %0,%1,%2,%0;" : "+l"(d) : "l"(a), "l"(b));
}
__device__ __forceinline__ float2 unpk(unsigned long long v) {
    float2 f;
    asm("mov.b64 {%0,%1},%2;" : "=f"(f.x), "=f"(f.y) : "l"(v));
    return f;
}

// ---------------------------------------------------------------------------
// fp32 SGEMM with f32x2 inner loop: C[M,N] = A[M,K] @ B[K,N] + bias[N]
// BM=128, BN=128, BK=8, 256 threads, 8x8 per thread (n packed in pairs).
// ---------------------------------------------------------------------------
__global__ void __launch_bounds__(256)
sgemm_bias_kernel(const float* __restrict__ A, const float* __restrict__ B,
                  const float* __restrict__ bias, float* __restrict__ C,
                  int M, int N, int K)
{
    constexpr int BM = 128, BN = 128, BK = 8, TM = 8, TN = 8;
    __shared__ __align__(16) float As[BK][BM];
    __shared__ __align__(16) float Bs[BK][BN];

    const int tid = threadIdx.x;
    const int bm = blockIdx.y * BM;
    const int bn = blockIdx.x * BN;

    const int tx = tid % (BN / TN);
    const int ty = tid / (BN / TN);
    const int row0 = ty * TM;
    const int col0 = tx * TN;

    const int aRow  = tid / (BK / 4);
    const int aCol4 = (tid % (BK / 4)) * 4;
    const int bRow  = tid / (BN / 4);
    const int bCol4 = (tid % (BN / 4)) * 4;

    const float* Aptr = A + (size_t)bm * K;
    const float* Bptr = B + bn;

    unsigned long long acc[TM][TN / 2];
#pragma unroll
    for (int i = 0; i < TM; i++)
#pragma unroll
        for (int j = 0; j < TN / 2; j++) acc[i][j] = 0ull;

    for (int k0 = 0; k0 < K; k0 += BK) {
        float4 a4 = *(const float4*)(Aptr + (size_t)aRow * K + k0 + aCol4);
        As[aCol4 + 0][aRow] = a4.x;
        As[aCol4 + 1][aRow] = a4.y;
        As[aCol4 + 2][aRow] = a4.z;
        As[aCol4 + 3][aRow] = a4.w;
        *(float4*)&Bs[bRow][bCol4] =
            *(const float4*)(Bptr + (size_t)(k0 + bRow) * N + bCol4);
        __syncthreads();

#pragma unroll
        for (int k = 0; k < BK; k++) {
            unsigned long long ra[TM];
#pragma unroll
            for (int i = 0; i < TM; i++) ra[i] = dup2(As[k][row0 + i]);
            const ulonglong2* bp = (const ulonglong2*)&Bs[k][col0];
            ulonglong2 rb0 = bp[0];
            ulonglong2 rb1 = bp[1];
#pragma unroll
            for (int i = 0; i < TM; i++) {
                fma2(acc[i][0], ra[i], rb0.x);
                fma2(acc[i][1], ra[i], rb0.y);
                fma2(acc[i][2], ra[i], rb1.x);
                fma2(acc[i][3], ra[i], rb1.y);
            }
        }
        __syncthreads();
    }

    float4 bv0 = *(const float4*)(bias + bn + col0);
    float4 bv1 = *(const float4*)(bias + bn + col0 + 4);
#pragma unroll
    for (int i = 0; i < TM; i++) {
        const size_t gr = (size_t)(bm + row0 + i);
        float2 a0 = unpk(acc[i][0]);
        float2 a1 = unpk(acc[i][1]);
        float2 a2 = unpk(acc[i][2]);
        float2 a3 = unpk(acc[i][3]);
        float4 v0 = make_float4(a0.x + bv0.x, a0.y + bv0.y,
                                a1.x + bv0.z, a1.y + bv0.w);
        float4 v1 = make_float4(a2.x + bv1.x, a2.y + bv1.y,
                                a3.x + bv1.z, a3.y + bv1.w);
        *(float4*)(C + gr * N + bn + col0)     = v0;
        *(float4*)(C + gr * N + bn + col0 + 4) = v1;
    }
}

// ---------------------------------------------------------------------------
// Persistent recurrence kernel: all 255 steps in one launch.
// Grid: 128 blocks (8 n-tiles x 2 b-tiles x 8 k-splits), 512 threads,
// 1 block/SM guaranteed (smem 82KB, launch_bounds(512,1)) => all co-resident
// => device-wide software barrier is deadlock-free.
// Each block: caches its W slice [128k][128n] in smem ONCE for all steps.
// Per step: partial = h_prev[b-tile][k-slice] @ Wslice -> g_part[ks];
//           barrier; every block reduces 16 b-rows of its (n,b) tile
//           (sum 8 partials + xh, tanh) -> h_t; barrier.
// ---------------------------------------------------------------------------
#define HS_STRIDE 132
#define SMEM_BYTES ((128 * 128 + 2 * 16 * HS_STRIDE) * 4)

__global__ void __launch_bounds__(512, 1)
rnn_persistent_kernel(const float* __restrict__ W,
                      const float* __restrict__ xh,
                      float* __restrict__ hs)
{
    extern __shared__ __align__(16) float smem[];
    float* Ws = smem;                     // [128][128]
    float* Hs = smem + 128 * 128;         // [2][16][HS_STRIDE]

    const int tid = threadIdx.x;
    const int bx  = blockIdx.x;
    const int ks  = bx & 7;          // k-split 0..7
    const int bt  = (bx >> 3) & 1;   // b-tile  0..1
    const int nt  = bx >> 4;         // n-tile  0..7
    const int k0  = ks * 128;
    const int b0  = bt * 128;
    const int n0  = nt * 128;

    const int lane = tid & 31;
    const int w    = tid >> 5;
    const int bb4  = ((w & 3) * 8 + (lane >> 2)) * 4;   // 0..124 step 4
    const int nn8  = ((w >> 2) * 4 + (lane & 3)) * 8;   // 0..120 step 8

    // Load W slice once: Ws[k][n] = W[k0+k][n0+n]
    {
        const int row  = tid >> 5;         // 0..15
        const int col4 = (tid & 31) * 4;   // 0..124
        for (int r = row; r < 128; r += 16)
            *(float4*)&Ws[r * 128 + col4] =
                *(const float4*)(W + (size_t)(k0 + r) * H_DIM + n0 + col4);
    }

    // h staging indices (read [b][k] row-major, store transposed [k][b])
    const int hrow  = tid >> 2;        // 0..127 (b)
    const int hcol4 = (tid & 3) * 4;   // 0,4,8,12 (k within chunk)

    __syncthreads();

    for (int t = 1; t < T_DIM; t++) {
        const float* h_prev = hs + (size_t)(t - 1) * BH;
        const float* xh_t   = xh + (size_t)t * BH;
        float*       h_out  = hs + (size_t)t * BH;

        unsigned long long acc[4][4];
#pragma unroll
        for (int i = 0; i < 4; i++)
#pragma unroll
            for (int j = 0; j < 4; j++) acc[i][j] = 0ull;

        float4 hreg = *(const float4*)(h_prev + (size_t)(b0 + hrow) * H_DIM
                                       + k0 + hcol4);
        {
            float* hb = Hs;  // buf 0
            hb[(hcol4 + 0) * HS_STRIDE + hrow] = hreg.x;
            hb[(hcol4 + 1) * HS_STRIDE + hrow] = hreg.y;
            hb[(hcol4 + 2) * HS_STRIDE + hrow] = hreg.z;
            hb[(hcol4 + 3) * HS_STRIDE + hrow] = hreg.w;
        }
        __syncthreads();

        for (int c = 0; c < 8; c++) {
            const int buf = c & 1;
            if (c < 7)
                hreg = *(const float4*)(h_prev + (size_t)(b0 + hrow) * H_DIM
                                        + k0 + (c + 1) * 16 + hcol4);

            const float* hb = Hs + buf * 16 * HS_STRIDE;
            const float* wb = Ws + c * 16 * 128;
#pragma unroll
            for (int kk = 0; kk < 16; kk++) {
                float4 h4 = *(const float4*)&hb[kk * HS_STRIDE + bb4];
                const ulonglong2* wp = (const ulonglong2*)&wb[kk * 128 + nn8];
                ulonglong2 wa = wp[0];
                ulonglong2 wc = wp[1];
                unsigned long long d0 = dup2(h4.x);
                unsigned long long d1 = dup2(h4.y);
                unsigned long long d2 = dup2(h4.z);
                unsigned long long d3 = dup2(h4.w);
                fma2(acc[0][0], d0, wa.x); fma2(acc[0][1], d0, wa.y);
                fma2(acc[0][2], d0, wc.x); fma2(acc[0][3], d0, wc.y);
                fma2(acc[1][0], d1, wa.x); fma2(acc[1][1], d1, wa.y);
                fma2(acc[1][2], d1, wc.x); fma2(acc[1][3], d1, wc.y);
                fma2(acc[2][0], d2, wa.x); fma2(acc[2][1], d2, wa.y);
                fma2(acc[2][2], d2, wc.x); fma2(acc[2][3], d2, wc.y);
                fma2(acc[3][0], d3, wa.x); fma2(acc[3][1], d3, wa.y);
                fma2(acc[3][2], d3, wc.x); fma2(acc[3][3], d3, wc.y);
            }

            if (c < 7) {
                float* hb2 = Hs + (1 - buf) * 16 * HS_STRIDE;
                hb2[(hcol4 + 0) * HS_STRIDE + hrow] = hreg.x;
                hb2[(hcol4 + 1) * HS_STRIDE + hrow] = hreg.y;
                hb2[(hcol4 + 2) * HS_STRIDE + hrow] = hreg.z;
                hb2[(hcol4 + 3) * HS_STRIDE + hrow] = hreg.w;
            }
            __syncthreads();
        }

        // Write partial tile (16B stores, n-pairs already packed)
        {
            float* part = g_part + (size_t)ks * BH;
#pragma unroll
            for (int i = 0; i < 4; i++) {
                float* dst = part + (size_t)(b0 + bb4 + i) * H_DIM + n0 + nn8;
                ((ulonglong2*)dst)[0] = make_ulonglong2(acc[i][0], acc[i][1]);
                ((ulonglong2*)dst)[1] = make_ulonglong2(acc[i][2], acc[i][3]);
            }
        }

        // ---- barrier A (all partials visible) ----
        __threadfence();
        __syncthreads();
        if (tid == 0) {
            atomicAdd(&g_bar, 1u);
            const unsigned target = (unsigned)(2 * t - 1) * NBLK;
            while (*(volatile unsigned*)&g_bar < target) { }
            __threadfence();
        }
        __syncthreads();

        // ---- distributed reduction: 16 b-rows of tile (nt,bt) per block ----
        {
            const int r  = tid >> 5;          // 0..15
            const int c4 = (tid & 31) * 4;    // 0..124
            const size_t off = (size_t)(b0 + ks * 16 + r) * H_DIM + n0 + c4;
            float4 s = *(const float4*)(xh_t + off);
#pragma unroll
            for (int sp = 0; sp < KSPLIT; sp++) {
                float4 p = *(const float4*)(g_part + (size_t)sp * BH + off);
                s.x += p.x; s.y += p.y; s.z += p.z; s.w += p.w;
            }
            float4 o;
            o.x = tanhf(s.x);
            o.y = tanhf(s.y);
            o.z = tanhf(s.z);
            o.w = tanhf(s.w);
            *(float4*)(h_out + off) = o;
        }

        // ---- barrier B (h_t visible for next step) ----
        if (t < T_DIM - 1) {
            __threadfence();
            __syncthreads();
            if (tid == 0) {
                atomicAdd(&g_bar, 1u);
                const unsigned target = (unsigned)(2 * t) * NBLK;
                while (*(volatile unsigned*)&g_bar < target) { }
                __threadfence();
            }
            __syncthreads();
        }
    }
}

// h_0 = tanh(xh_0); also resets the persistent kernel's barrier counter.
__global__ void __launch_bounds__(256)
init_kernel(const float* __restrict__ x, float* __restrict__ y)
{
    if (blockIdx.x == 0 && threadIdx.x == 0) g_bar = 0u;
    const size_t i = ((size_t)blockIdx.x * blockDim.x + threadIdx.x) * 4;
    float4 v = *(const float4*)(x + i);
    v.x = tanhf(v.x);
    v.y = tanhf(v.y);
    v.z = tanhf(v.z);
    v.w = tanhf(v.w);
    *(float4*)(y + i) = v;
}

__global__ void __launch_bounds__(256)
copy_kernel(const float* __restrict__ src, float* __restrict__ dst)
{
    const size_t i = ((size_t)blockIdx.x * blockDim.x + threadIdx.x) * 4;
    *(float4*)(dst + i) = *(const float4*)(src + i);
}

// ---------------------------------------------------------------------------
extern "C" void kernel_launch(void* const* d_in, const int* in_sizes, int n_in,
                              void* d_out, int out_size)
{
    const float* inputs  = (const float*)d_in[0]; // [T,B,V]
    const float* W_xh    = (const float*)d_in[1]; // [V,H]
    const float* W_hh    = (const float*)d_in[2]; // [H,H]
    const float* b_h     = (const float*)d_in[3]; // [H]
    const float* W_dense = (const float*)d_in[4]; // [H,V]
    const float* b_dense = (const float*)d_in[5]; // [V]
    float* out = (float*)d_out;

    float *xh = nullptr, *hs = nullptr;
    cudaGetSymbolAddress((void**)&xh, g_xh);
    cudaGetSymbolAddress((void**)&hs, g_hs);

    cudaFuncSetAttribute(rnn_persistent_kernel,
                         cudaFuncAttributeMaxDynamicSharedMemorySize,
                         SMEM_BYTES);

    // 1) xh = inputs @ W_xh + b_h : [65536,512] x [512,1024]
    {
        dim3 grid(H_DIM / 128, M_ALL / 128);
        sgemm_bias_kernel<<<grid, 256>>>(inputs, W_xh, b_h, xh,
                                         M_ALL, H_DIM, V_DIM);
    }

    // 2) h_0 = tanh(xh_0) + barrier reset; then all 255 steps in one kernel
    init_kernel<<<BH / (256 * 4), 256>>>(xh, hs);
    rnn_persistent_kernel<<<NBLK, 512, SMEM_BYTES>>>(W_hh, xh, hs);

    // 3) outputs = hs @ W_dense + b_dense : [65536,1024] x [1024,512]
    {
        dim3 grid(V_DIM / 128, M_ALL / 128);
        sgemm_bias_kernel<<<grid, 256>>>(hs, W_dense, b_dense, out,
                                         M_ALL, V_DIM, H_DIM);
    }

    // 4) state = h_{T-1}
    if (out_size >= TBV + BH) {
        copy_kernel<<<BH / (256 * 4), 256>>>(hs + (size_t)(T_DIM - 1) * BH,
                                             out + TBV);
    }
}